// round 10
// baseline (speedup 1.0000x reference)
#include <cuda_runtime.h>
#include <math.h>
#include <float.h>

#define BB 16
#define TT 512
#define DD 512

typedef unsigned long long ull;
__device__ __forceinline__ ull umax64(ull a, ull b) { return a > b ? a : b; }
__device__ __forceinline__ ull umin64(ull a, ull b) { return a < b ? a : b; }
__device__ __forceinline__ float ex2f(float x) {
    float y; asm("ex2.approx.ftz.f32 %0, %1;" : "=f"(y) : "f"(x)); return y;
}

// ---------------- scratch (static __device__ — no allocations) ----------------
__device__ float g_xtr[BB * DD];                    // x_trans (before +b_lin)

// ---------------- fused: 4 series per block, 2 packed real FFTs (radix-4) ----------------
__global__ void __launch_bounds__(256, 5) k_fused(const float* __restrict__ x,
                                                  const float* __restrict__ W_trend,
                                                  const float* __restrict__ b_trend,
                                                  const float* __restrict__ W_lin) {
    __shared__ float2 s_pp[2][1024];    // FFT ping-pong; buf0 later = spectrum (float2),
                                        // buf1 later = rem (as float[2048])
    __shared__ float2 s_trig[512];      // {cos, sin}(2*pi*j/512)
    __shared__ float  s_x[4][512];
    __shared__ float  s_cse[4][545];    // extended cumsum: index i+16, i in [-16, 528]
    __shared__ int    s_wk[4][4];
    __shared__ float  s_wr[4][4], s_wi[4][4];
    __shared__ float  s_red[4][8];

    int tid = threadIdx.x;
    int lane = tid & 31, w = tid >> 5;
    int bidx = blockIdx.x;
    int b  = bidx >> 7;                 // 128 blocks per batch (512/4)
    int d0 = (bidx & 127) << 2;

    // issue strided global loads first (latency hidden by trig below)
    const float* xp = x + ((size_t)b * TT + tid) * DD + d0;
    float4 v0 = *(const float4*)xp;
    float4 v1 = *(const float4*)(xp + (size_t)256 * DD);

    // trig table: one sincospif; second half via cos(pi+a) = -cos(a)
    {
        float s0, c0;
        sincospif((float)tid * (1.0f / 256.0f), &s0, &c0);
        s_trig[tid]       = make_float2(c0, s0);
        s_trig[tid + 256] = make_float2(-c0, -s0);
    }

    // stash x; pack fft0 = x(d0) + i x(d0+1), fft1 = x(d0+2) + i x(d0+3)
    s_x[0][tid] = v0.x; s_x[1][tid] = v0.y; s_x[2][tid] = v0.z; s_x[3][tid] = v0.w;
    s_x[0][tid + 256] = v1.x; s_x[1][tid + 256] = v1.y;
    s_x[2][tid + 256] = v1.z; s_x[3][tid + 256] = v1.w;
    s_pp[0][tid]             = make_float2(v0.x, v0.y);
    s_pp[0][tid + 256]       = make_float2(v1.x, v1.y);
    s_pp[0][512 + tid]       = make_float2(v0.z, v0.w);
    s_pp[0][512 + tid + 256] = make_float2(v1.z, v1.w);

    // ---- 4 radix-4 Stockham stages (Ns = 1,4,16,64), 2 FFTs in parallel ----
    int cur = 0;
    #pragma unroll
    for (int st = 0; st < 4; st++) {
        int Ns = 1 << (2 * st);
        int shiftm = 7 - 2 * st;         // twiddle idx = k * (128/Ns)
        __syncthreads();
        int f = tid >> 7;                // fft id
        int j = tid & 127;
        int k = j & (Ns - 1);
        int base = f << 9;
        float2 a0 = s_pp[cur][base + j];
        float2 a1 = s_pp[cur][base + j + 128];
        float2 a2 = s_pp[cur][base + j + 256];
        float2 a3 = s_pp[cur][base + j + 384];
        int m = k << shiftm;
        float2 w1 = s_trig[m], w2 = s_trig[2 * m], w3 = s_trig[3 * m];
        // t = W*x, W = (c, -s)
        float t1r = w1.x * a1.x + w1.y * a1.y, t1i = w1.x * a1.y - w1.y * a1.x;
        float t2r = w2.x * a2.x + w2.y * a2.y, t2i = w2.x * a2.y - w2.y * a2.x;
        float t3r = w3.x * a3.x + w3.y * a3.y, t3i = w3.x * a3.y - w3.y * a3.x;
        float y0r = a0.x + t1r + t2r + t3r, y0i = a0.y + t1i + t2i + t3i;
        float y2r = a0.x - t1r + t2r - t3r, y2i = a0.y - t1i + t2i - t3i;
        float y1r = a0.x + t1i - t2r - t3i, y1i = a0.y - t1r - t2i + t3r;
        float y3r = a0.x - t1i - t2r + t3i, y3i = a0.y + t1r - t2i - t3r;
        int o = base + 4 * j - 3 * k;
        int nxt = cur ^ 1;
        s_pp[nxt][o]          = make_float2(y0r, y0i);
        s_pp[nxt][o + Ns]     = make_float2(y1r, y1i);
        s_pp[nxt][o + 2 * Ns] = make_float2(y2r, y2i);
        s_pp[nxt][o + 3 * Ns] = make_float2(y3r, y3i);
        cur = nxt;
    }
    // ---- final radix-2 stage (Ns = 256), each thread does both FFTs ----
    __syncthreads();
    {
        int k = tid;
        float2 wv = s_trig[k];
        int nxt = cur ^ 1;
        #pragma unroll
        for (int f = 0; f < 2; f++) {
            int base = f << 9;
            float2 a = s_pp[cur][base + k];
            float2 c = s_pp[cur][base + k + 256];
            float tr = wv.x * c.x + wv.y * c.y, ti = wv.x * c.y - wv.y * c.x;
            s_pp[nxt][base + k]       = make_float2(a.x + tr, a.y + ti);
            s_pp[nxt][base + k + 256] = make_float2(a.x - tr, a.y - ti);
        }
        cur = nxt;                        // final spectrum in buf 1
    }
    __syncthreads();

    // ---- unpack: spectrum of series s as float2 at s_pp[0][s*256 + k], k=1..255 ----
    if (tid >= 1) {
        int k = tid, mk = 512 - tid;
        #pragma unroll
        for (int f = 0; f < 2; f++) {
            int base = f << 9;
            float2 Z = s_pp[1][base + k];
            float2 M = s_pp[1][base + mk];
            float Xar = 0.5f * (Z.x + M.x), Xai = 0.5f * (Z.y - M.y);
            float Xbr = 0.5f * (Z.y + M.y), Xbi = 0.5f * (M.x - Z.x);
            s_pp[0][(2 * f) * 256 + k]     = make_float2(Xar, Xai);
            s_pp[0][(2 * f + 1) * 256 + k] = make_float2(Xbr, Xbi);
        }
    }
    __syncthreads();

    // ---- warp top-4 per series (warps 0..3), key = amp_bits<<32 | (511-k) ----
    if (w < 4) {
        const float2* Xs = &s_pp[0][w * 256];
        ull c0 = 0, c1 = 0, c2 = 0, c3 = 0;
        #pragma unroll
        for (int j = 0; j < 8; j++) {
            int k = lane + 32 * j;
            float2 X = Xs[k];
            float a = X.x * X.x + X.y * X.y;
            ull p = (k == 0) ? 0ull
                  : (((ull)__float_as_uint(a) << 32) | (ull)(511 - k));
            ull t;
            t = umin64(c0, p); c0 = umax64(c0, p); p = t;
            t = umin64(c1, p); c1 = umax64(c1, p); p = t;
            t = umin64(c2, p); c2 = umax64(c2, p); p = t;
            c3 = umax64(c3, p);
        }
        #pragma unroll
        for (int off = 16; off; off >>= 1) {
            ull o0 = __shfl_xor_sync(0xffffffffu, c0, off);
            ull o1 = __shfl_xor_sync(0xffffffffu, c1, off);
            ull o2 = __shfl_xor_sync(0xffffffffu, c2, off);
            ull o3 = __shfl_xor_sync(0xffffffffu, c3, off);
            bool mf = c0 > o0;
            ull u0 = mf ? c0 : o0, u1 = mf ? c1 : o1, u2 = mf ? c2 : o2, u3 = mf ? c3 : o3;
            ull v0_ = mf ? o0 : c0, v1_ = mf ? o1 : c1, v2_ = mf ? o2 : c2, v3_ = mf ? o3 : c3;
            ull A0 = umax64(u0, v3_), A1 = umax64(u1, v2_);
            ull A2 = umax64(u2, v1_), A3 = umax64(u3, v0_);
            ull B0 = umax64(A0, A2), B2 = umin64(A0, A2);
            ull B1 = umax64(A1, A3), B3 = umin64(A1, A3);
            c0 = umax64(B0, B1); c1 = umin64(B0, B1);
            c2 = umax64(B2, B3); c3 = umin64(B2, B3);
        }
        if (lane == 0) {
            int k0 = 511 - (int)(c0 & 0xffffffffull);
            int k1 = 511 - (int)(c1 & 0xffffffffull);
            int k2 = 511 - (int)(c2 & 0xffffffffull);
            int k3 = 511 - (int)(c3 & 0xffffffffull);
            float2 X0 = Xs[k0], X1 = Xs[k1], X2 = Xs[k2], X3 = Xs[k3];
            s_wk[w][0] = k0; s_wr[w][0] = X0.x; s_wi[w][0] = X0.y;
            s_wk[w][1] = k1; s_wr[w][1] = X1.x; s_wi[w][1] = X1.y;
            s_wk[w][2] = k2; s_wr[w][2] = X2.x; s_wi[w][2] = X2.y;
            s_wk[w][3] = k3; s_wr[w][3] = X3.x; s_wi[w][3] = X3.y;
        }
    }
    __syncthreads();

    // ---- season + remainder; rem (float) aliases buf1: series s -> remall + s*512 ----
    float* remall = (float*)&s_pp[1][0];
    #pragma unroll
    for (int s = 0; s < 4; s++) {
        int   kk0 = s_wk[s][0], kk1 = s_wk[s][1], kk2 = s_wk[s][2], kk3 = s_wk[s][3];
        float r0 = s_wr[s][0], r1 = s_wr[s][1], r2 = s_wr[s][2], r3 = s_wr[s][3];
        float i0 = s_wi[s][0], i1 = s_wi[s][1], i2 = s_wi[s][2], i3 = s_wi[s][3];
        float* remp = remall + s * 512;
        #pragma unroll
        for (int tt = 0; tt < 2; tt++) {
            int t = tid + tt * 256;
            float2 T0 = s_trig[(kk0 * t) & 511];
            float2 T1 = s_trig[(kk1 * t) & 511];
            float2 T2 = s_trig[(kk2 * t) & 511];
            float2 T3 = s_trig[(kk3 * t) & 511];
            float se = r0 * T0.x - i0 * T0.y
                     + r1 * T1.x - i1 * T1.y
                     + r2 * T2.x - i2 * T2.y
                     + r3 * T3.x - i3 * T3.y;
            remp[t] = s_x[s][t] - se * (2.0f / 512.0f);
        }
    }
    __syncthreads();

    // ---- 4 parallel exclusive cumsums with linear-extension pads ----
    // cs_ext[i] (i in [-16,528]) at s_cse[s][16+i]:
    //   i<0: i*rem0 ; 0..512: exclusive cumsum ; >512: total + (i-512)*remL
    if (w < 4) {
        const float* rm = remall + w * 512;
        float* cse = s_cse[w];
        int base = lane * 16;
        float run = 0.f, pref[16];
        #pragma unroll
        for (int i = 0; i < 16; i++) { pref[i] = run; run += rm[base + i]; }
        float inc = run;
        #pragma unroll
        for (int sft = 1; sft < 32; sft <<= 1) {
            float v = __shfl_up_sync(0xffffffffu, inc, sft);
            if (lane >= sft) inc += v;
        }
        float excl = inc - run;
        #pragma unroll
        for (int i = 0; i < 16; i++) cse[16 + base + i] = excl + pref[i];
        float total = __shfl_sync(0xffffffffu, inc, 31);
        if (lane == 31) cse[16 + 512] = total;
        if (lane < 16) {
            float rem0 = rm[0], remL = rm[511];
            cse[lane] = (float)(lane - 16) * rem0;                      // i = lane-16
            cse[16 + 513 + lane] = total + (float)(lane + 1) * remL;    // i = 513+lane
        }
    }
    __syncthreads();

    // ---- trend + W_lin reduce, 4 series ----
    const float LOG2E = 1.44269504f;
    float Wt2[6], bt2[6];
    #pragma unroll
    for (int j = 0; j < 6; j++) { Wt2[j] = W_trend[j] * LOG2E; bt2[j] = b_trend[j] * LOG2E; }
    const int   koff[6] = {2, 4, 6, 8, 12, 16};        // k/2
    const float inv[6] = {0.25f, 0.125f, 1.f / 12.f, 0.0625f, 1.f / 24.f, 0.03125f};
    float wl0 = W_lin[tid], wl1 = W_lin[tid + 256];

    float accv[4];
    #pragma unroll
    for (int s = 0; s < 4; s++) {
        const float* rem_s = remall + s * 512;
        const float* cse = s_cse[s] + 16;
        const float* x_s = s_x[s];
        float acc = 0.f;
        #pragma unroll
        for (int tt = 0; tt < 2; tt++) {
            int t = tid + tt * 256;
            float rem = rem_s[t];
            const float* cp = cse + t;
            float es = 0.f, ws = 0.f;
            #pragma unroll
            for (int j = 0; j < 6; j++) {
                float ssum = cp[koff[j]] - cp[-koff[j]];
                float e = ex2f(fmaf(rem, Wt2[j], bt2[j]));
                es += e;
                ws = fmaf(e, ssum * inv[j], ws);
            }
            float trend = __fdividef(ws, es);
            float xsum = 2.0f * x_s[t] - rem + trend;
            acc = fmaf(xsum, (tt ? wl1 : wl0), acc);
        }
        accv[s] = acc;
    }

    #pragma unroll
    for (int o = 16; o > 0; o >>= 1) {
        accv[0] += __shfl_down_sync(0xffffffffu, accv[0], o);
        accv[1] += __shfl_down_sync(0xffffffffu, accv[1], o);
        accv[2] += __shfl_down_sync(0xffffffffu, accv[2], o);
        accv[3] += __shfl_down_sync(0xffffffffu, accv[3], o);
    }
    if (lane == 0) {
        s_red[0][w] = accv[0]; s_red[1][w] = accv[1];
        s_red[2][w] = accv[2]; s_red[3][w] = accv[3];
    }
    __syncthreads();
    if (tid < 4) {
        float s = 0.f;
        #pragma unroll
        for (int ww = 0; ww < 8; ww++) s += s_red[tid][ww];
        g_xtr[blockIdx.x * 4 + tid] = s;
    }
}

// ---------------- final routing: (B,D)->(B,8), softplus noise, softmax, top-4 ----------------
__global__ void k_router(const float* __restrict__ noise, const float* __restrict__ W_r,
                         const float* __restrict__ b_r, const float* __restrict__ W_noise,
                         const float* __restrict__ b_noise, const float* __restrict__ b_lin,
                         float* __restrict__ out) {
    int b = blockIdx.x;
    int tid = threadIdx.x;
    int m = tid & 7, c = tid >> 3;
    __shared__ float sp[256], sn[256];
    __shared__ float slog[8];
    const float* xt = g_xtr + b * DD;
    float blin = b_lin[0];
    float p = 0.f, pn = 0.f;
    #pragma unroll
    for (int i = 0; i < 16; i++) {
        int d = c * 16 + i;
        float v = xt[d] + blin;
        p  = fmaf(v, W_r[d * 8 + m], p);
        pn = fmaf(v, W_noise[d * 8 + m], pn);
    }
    sp[tid] = p; sn[tid] = pn;
    __syncthreads();
    if (tid < 8) {
        float P = 0.f, N = 0.f;
        for (int cc = 0; cc < 32; cc++) { P += sp[cc * 8 + tid]; N += sn[cc * 8 + tid]; }
        float base = P + b_r[tid];
        float nl = N + b_noise[tid];
        float ns = log1pf(expf(-fabsf(nl))) + fmaxf(nl, 0.f);   // softplus
        slog[tid] = base + noise[b * 8 + tid] * ns;
    }
    __syncthreads();
    if (tid == 0) {
        float lg[8], mx = -FLT_MAX;
        #pragma unroll
        for (int i = 0; i < 8; i++) { lg[i] = slog[i]; mx = fmaxf(mx, lg[i]); }
        float es = 0.f, pw[8];
        #pragma unroll
        for (int i = 0; i < 8; i++) { pw[i] = expf(lg[i] - mx); es += pw[i]; }
        #pragma unroll
        for (int i = 0; i < 8; i++) pw[i] /= es;
        #pragma unroll
        for (int i = 0; i < 8; i++) {
            int rank = 0;
            #pragma unroll
            for (int j = 0; j < 8; j++)
                if (pw[j] > pw[i] || (pw[j] == pw[i] && j < i)) rank++;
            out[b * 8 + i] = (rank < 4) ? pw[i] : 0.f;
        }
    }
}

// ---------------- launch ----------------
extern "C" void kernel_launch(void* const* d_in, const int* in_sizes, int n_in,
                              void* d_out, int out_size) {
    const float* x       = (const float*)d_in[0];
    const float* noise   = (const float*)d_in[1];
    const float* W_r     = (const float*)d_in[2];
    const float* b_r     = (const float*)d_in[3];
    const float* W_noise = (const float*)d_in[4];
    const float* b_noise = (const float*)d_in[5];
    const float* W_trend = (const float*)d_in[6];
    const float* b_trend = (const float*)d_in[7];
    const float* W_lin   = (const float*)d_in[8];
    const float* b_lin   = (const float*)d_in[9];
    float* out = (float*)d_out;

    k_fused<<<BB * DD / 4, 256>>>(x, W_trend, b_trend, W_lin);
    k_router<<<16, 256>>>(noise, W_r, b_r, W_noise, b_noise, b_lin, out);
}

// round 11
// speedup vs baseline: 1.1046x; 1.1046x over previous
#include <cuda_runtime.h>
#include <math.h>
#include <float.h>

#define BB 16
#define TT 512
#define DD 512

typedef unsigned long long ull;
__device__ __forceinline__ ull umax64(ull a, ull b) { return a > b ? a : b; }
__device__ __forceinline__ ull umin64(ull a, ull b) { return a < b ? a : b; }
__device__ __forceinline__ float ex2f(float x) {
    float y; asm("ex2.approx.ftz.f32 %0, %1;" : "=f"(y) : "f"(x)); return y;
}

// ---------------- scratch (static __device__ — no allocations) ----------------
__device__ float g_xtr[BB * DD];                    // x_trans (before +b_lin)

// ---------------- fused: 4 series per block, 2 packed real FFTs (radix-4) ----------------
__global__ void __launch_bounds__(256, 5) k_fused(const float* __restrict__ x,
                                                  const float* __restrict__ W_trend,
                                                  const float* __restrict__ b_trend,
                                                  const float* __restrict__ W_lin) {
    __shared__ float2 s_pp[2][1024];    // FFT ping-pong; buf0 = spectrum, buf1 later = rem
    __shared__ float2 s_trig[512];      // {cos, sin}(2*pi*j/512)
    __shared__ float  s_cse[4][545];    // extended cumsum: index i+16, i in [-16, 528]
    __shared__ int    s_wk[4][4];
    __shared__ float  s_wr[4][4], s_wi[4][4];
    __shared__ float  s_red[4][8];

    int tid = threadIdx.x;
    int lane = tid & 31, w = tid >> 5;
    int bidx = blockIdx.x;
    int b  = bidx >> 7;                 // 128 blocks per batch (512/4)
    int d0 = (bidx & 127) << 2;

    // issue strided global loads first (latency hidden by trig below)
    const float* xp = x + ((size_t)b * TT + tid) * DD + d0;
    float4 v0 = *(const float4*)xp;
    float4 v1 = *(const float4*)(xp + (size_t)256 * DD);

    // trig table: one sincospif; second half via cos(pi+a) = -cos(a)
    {
        float s0, c0;
        sincospif((float)tid * (1.0f / 256.0f), &s0, &c0);
        s_trig[tid]       = make_float2(c0, s0);
        s_trig[tid + 256] = make_float2(-c0, -s0);
    }

    // x values for this thread's positions (t = tid, tid+256), all 4 series -> registers
    float xv[4][2];
    xv[0][0] = v0.x; xv[1][0] = v0.y; xv[2][0] = v0.z; xv[3][0] = v0.w;
    xv[0][1] = v1.x; xv[1][1] = v1.y; xv[2][1] = v1.z; xv[3][1] = v1.w;

    // pack fft0 = x(d0) + i x(d0+1), fft1 = x(d0+2) + i x(d0+3)
    s_pp[0][tid]             = make_float2(v0.x, v0.y);
    s_pp[0][tid + 256]       = make_float2(v1.x, v1.y);
    s_pp[0][512 + tid]       = make_float2(v0.z, v0.w);
    s_pp[0][512 + tid + 256] = make_float2(v1.z, v1.w);

    // ---- 4 radix-4 Stockham stages (Ns = 1,4,16,64), 2 FFTs in parallel ----
    int cur = 0;
    #pragma unroll
    for (int st = 0; st < 4; st++) {
        int Ns = 1 << (2 * st);
        int shiftm = 7 - 2 * st;         // twiddle idx = k * (128/Ns)
        __syncthreads();
        int f = tid >> 7;                // fft id
        int j = tid & 127;
        int k = j & (Ns - 1);
        int base = f << 9;
        float2 a0 = s_pp[cur][base + j];
        float2 a1 = s_pp[cur][base + j + 128];
        float2 a2 = s_pp[cur][base + j + 256];
        float2 a3 = s_pp[cur][base + j + 384];
        int m = k << shiftm;
        float2 w1 = s_trig[m], w2 = s_trig[2 * m], w3 = s_trig[3 * m];
        // t = W*x, W = (c, -s)
        float t1r = w1.x * a1.x + w1.y * a1.y, t1i = w1.x * a1.y - w1.y * a1.x;
        float t2r = w2.x * a2.x + w2.y * a2.y, t2i = w2.x * a2.y - w2.y * a2.x;
        float t3r = w3.x * a3.x + w3.y * a3.y, t3i = w3.x * a3.y - w3.y * a3.x;
        float y0r = a0.x + t1r + t2r + t3r, y0i = a0.y + t1i + t2i + t3i;
        float y2r = a0.x - t1r + t2r - t3r, y2i = a0.y - t1i + t2i - t3i;
        float y1r = a0.x + t1i - t2r - t3i, y1i = a0.y - t1r - t2i + t3r;
        float y3r = a0.x - t1i - t2r + t3i, y3i = a0.y + t1r - t2i - t3r;
        int o = base + 4 * j - 3 * k;
        int nxt = cur ^ 1;
        s_pp[nxt][o]          = make_float2(y0r, y0i);
        s_pp[nxt][o + Ns]     = make_float2(y1r, y1i);
        s_pp[nxt][o + 2 * Ns] = make_float2(y2r, y2i);
        s_pp[nxt][o + 3 * Ns] = make_float2(y3r, y3i);
        cur = nxt;
    }
    // ---- final radix-2 stage (Ns = 256), each thread does both FFTs ----
    __syncthreads();
    {
        int k = tid;
        float2 wv = s_trig[k];
        int nxt = cur ^ 1;
        #pragma unroll
        for (int f = 0; f < 2; f++) {
            int base = f << 9;
            float2 a = s_pp[cur][base + k];
            float2 c = s_pp[cur][base + k + 256];
            float tr = wv.x * c.x + wv.y * c.y, ti = wv.x * c.y - wv.y * c.x;
            s_pp[nxt][base + k]       = make_float2(a.x + tr, a.y + ti);
            s_pp[nxt][base + k + 256] = make_float2(a.x - tr, a.y - ti);
        }
        cur = nxt;                        // final spectrum in buf 1
    }
    __syncthreads();

    // ---- unpack: spectrum of series s as float2 at s_pp[0][s*256 + k], k=1..255 ----
    if (tid >= 1) {
        int k = tid, mk = 512 - tid;
        #pragma unroll
        for (int f = 0; f < 2; f++) {
            int base = f << 9;
            float2 Z = s_pp[1][base + k];
            float2 M = s_pp[1][base + mk];
            float Xar = 0.5f * (Z.x + M.x), Xai = 0.5f * (Z.y - M.y);
            float Xbr = 0.5f * (Z.y + M.y), Xbi = 0.5f * (M.x - Z.x);
            s_pp[0][(2 * f) * 256 + k]     = make_float2(Xar, Xai);
            s_pp[0][(2 * f + 1) * 256 + k] = make_float2(Xbr, Xbi);
        }
    }
    __syncthreads();

    // ---- warp top-4 per series (warps 0..3), key = amp_bits<<32 | (511-k) ----
    if (w < 4) {
        const float2* Xs = &s_pp[0][w * 256];
        ull c0 = 0, c1 = 0, c2 = 0, c3 = 0;
        #pragma unroll
        for (int j = 0; j < 8; j++) {
            int k = lane + 32 * j;
            float2 X = Xs[k];
            float a = X.x * X.x + X.y * X.y;
            ull p = (k == 0) ? 0ull
                  : (((ull)__float_as_uint(a) << 32) | (ull)(511 - k));
            ull t;
            t = umin64(c0, p); c0 = umax64(c0, p); p = t;
            t = umin64(c1, p); c1 = umax64(c1, p); p = t;
            t = umin64(c2, p); c2 = umax64(c2, p); p = t;
            c3 = umax64(c3, p);
        }
        #pragma unroll
        for (int off = 16; off; off >>= 1) {
            ull o0 = __shfl_xor_sync(0xffffffffu, c0, off);
            ull o1 = __shfl_xor_sync(0xffffffffu, c1, off);
            ull o2 = __shfl_xor_sync(0xffffffffu, c2, off);
            ull o3 = __shfl_xor_sync(0xffffffffu, c3, off);
            bool mf = c0 > o0;
            ull u0 = mf ? c0 : o0, u1 = mf ? c1 : o1, u2 = mf ? c2 : o2, u3 = mf ? c3 : o3;
            ull v0_ = mf ? o0 : c0, v1_ = mf ? o1 : c1, v2_ = mf ? o2 : c2, v3_ = mf ? o3 : c3;
            ull A0 = umax64(u0, v3_), A1 = umax64(u1, v2_);
            ull A2 = umax64(u2, v1_), A3 = umax64(u3, v0_);
            ull B0 = umax64(A0, A2), B2 = umin64(A0, A2);
            ull B1 = umax64(A1, A3), B3 = umin64(A1, A3);
            c0 = umax64(B0, B1); c1 = umin64(B0, B1);
            c2 = umax64(B2, B3); c3 = umin64(B2, B3);
        }
        if (lane == 0) {
            int k0 = 511 - (int)(c0 & 0xffffffffull);
            int k1 = 511 - (int)(c1 & 0xffffffffull);
            int k2 = 511 - (int)(c2 & 0xffffffffull);
            int k3 = 511 - (int)(c3 & 0xffffffffull);
            float2 X0 = Xs[k0], X1 = Xs[k1], X2 = Xs[k2], X3 = Xs[k3];
            s_wk[w][0] = k0; s_wr[w][0] = X0.x; s_wi[w][0] = X0.y;
            s_wk[w][1] = k1; s_wr[w][1] = X1.x; s_wi[w][1] = X1.y;
            s_wk[w][2] = k2; s_wr[w][2] = X2.x; s_wi[w][2] = X2.y;
            s_wk[w][3] = k3; s_wr[w][3] = X3.x; s_wi[w][3] = X3.y;
        }
    }
    __syncthreads();

    // ---- season + remainder; rem kept in registers AND stored (float) into buf1 ----
    float* remall = (float*)&s_pp[1][0];
    float remv[4][2];
    #pragma unroll
    for (int s = 0; s < 4; s++) {
        int   kk0 = s_wk[s][0], kk1 = s_wk[s][1], kk2 = s_wk[s][2], kk3 = s_wk[s][3];
        float r0 = s_wr[s][0], r1 = s_wr[s][1], r2 = s_wr[s][2], r3 = s_wr[s][3];
        float i0 = s_wi[s][0], i1 = s_wi[s][1], i2 = s_wi[s][2], i3 = s_wi[s][3];
        float* remp = remall + s * 512;
        #pragma unroll
        for (int tt = 0; tt < 2; tt++) {
            int t = tid + tt * 256;
            float2 T0 = s_trig[(kk0 * t) & 511];
            float2 T1 = s_trig[(kk1 * t) & 511];
            float2 T2 = s_trig[(kk2 * t) & 511];
            float2 T3 = s_trig[(kk3 * t) & 511];
            float se = r0 * T0.x - i0 * T0.y
                     + r1 * T1.x - i1 * T1.y
                     + r2 * T2.x - i2 * T2.y
                     + r3 * T3.x - i3 * T3.y;
            float rv = xv[s][tt] - se * (2.0f / 512.0f);
            remv[s][tt] = rv;
            remp[t] = rv;
        }
    }
    __syncthreads();

    // ---- 4 parallel cumsums, conflict-free pass-based scan ----
    // cs_ext[i] (i in [-16,528]) at s_cse[s][16+i]:
    //   i<0: i*rem0 ; 0..512: exclusive cumsum ; >512: total + (i-512)*remL
    if (w < 4) {
        const float* rm = remall + w * 512;
        float* cse = s_cse[w];
        float offset = 0.f;
        #pragma unroll
        for (int i = 0; i < 16; i++) {
            float v = rm[i * 32 + lane];
            float inc = v;
            #pragma unroll
            for (int sft = 1; sft < 32; sft <<= 1) {
                float u = __shfl_up_sync(0xffffffffu, inc, sft);
                if (lane >= sft) inc += u;
            }
            cse[16 + i * 32 + lane] = offset + (inc - v);   // exclusive
            offset += __shfl_sync(0xffffffffu, inc, 31);
        }
        if (lane == 31) cse[16 + 512] = offset;             // total
        if (lane < 16) {
            float rem0 = rm[0], remL = rm[511];
            cse[lane] = (float)(lane - 16) * rem0;                      // i = lane-16
            cse[16 + 513 + lane] = offset + (float)(lane + 1) * remL;   // i = 513+lane
        }
    }
    __syncthreads();

    // ---- trend + W_lin reduce, 4 series (rem & x from registers) ----
    const float LOG2E = 1.44269504f;
    float Wt2[6], bt2[6];
    #pragma unroll
    for (int j = 0; j < 6; j++) { Wt2[j] = W_trend[j] * LOG2E; bt2[j] = b_trend[j] * LOG2E; }
    const int   koff[6] = {2, 4, 6, 8, 12, 16};        // k/2
    const float inv[6] = {0.25f, 0.125f, 1.f / 12.f, 0.0625f, 1.f / 24.f, 0.03125f};
    float wl0 = W_lin[tid], wl1 = W_lin[tid + 256];

    float accv[4];
    #pragma unroll
    for (int s = 0; s < 4; s++) {
        const float* cse = s_cse[s] + 16;
        float acc = 0.f;
        #pragma unroll
        for (int tt = 0; tt < 2; tt++) {
            int t = tid + tt * 256;
            float rem = remv[s][tt];
            const float* cp = cse + t;
            float es = 0.f, ws = 0.f;
            #pragma unroll
            for (int j = 0; j < 6; j++) {
                float ssum = cp[koff[j]] - cp[-koff[j]];
                float e = ex2f(fmaf(rem, Wt2[j], bt2[j]));
                es += e;
                ws = fmaf(e, ssum * inv[j], ws);
            }
            float trend = __fdividef(ws, es);
            float xsum = 2.0f * xv[s][tt] - rem + trend;
            acc = fmaf(xsum, (tt ? wl1 : wl0), acc);
        }
        accv[s] = acc;
    }

    #pragma unroll
    for (int o = 16; o > 0; o >>= 1) {
        accv[0] += __shfl_down_sync(0xffffffffu, accv[0], o);
        accv[1] += __shfl_down_sync(0xffffffffu, accv[1], o);
        accv[2] += __shfl_down_sync(0xffffffffu, accv[2], o);
        accv[3] += __shfl_down_sync(0xffffffffu, accv[3], o);
    }
    if (lane == 0) {
        s_red[0][w] = accv[0]; s_red[1][w] = accv[1];
        s_red[2][w] = accv[2]; s_red[3][w] = accv[3];
    }
    __syncthreads();
    if (tid < 4) {
        float s = 0.f;
        #pragma unroll
        for (int ww = 0; ww < 8; ww++) s += s_red[tid][ww];
        g_xtr[blockIdx.x * 4 + tid] = s;
    }
}

// ---------------- final routing: (B,D)->(B,8), softplus noise, softmax, top-4 ----------------
__global__ void k_router(const float* __restrict__ noise, const float* __restrict__ W_r,
                         const float* __restrict__ b_r, const float* __restrict__ W_noise,
                         const float* __restrict__ b_noise, const float* __restrict__ b_lin,
                         float* __restrict__ out) {
    int b = blockIdx.x;
    int tid = threadIdx.x;
    int m = tid & 7, c = tid >> 3;
    __shared__ float sp[256], sn[256];
    __shared__ float slog[8];
    const float* xt = g_xtr + b * DD;
    float blin = b_lin[0];
    float p = 0.f, pn = 0.f;
    #pragma unroll
    for (int i = 0; i < 16; i++) {
        int d = c * 16 + i;
        float v = xt[d] + blin;
        p  = fmaf(v, W_r[d * 8 + m], p);
        pn = fmaf(v, W_noise[d * 8 + m], pn);
    }
    sp[tid] = p; sn[tid] = pn;
    __syncthreads();
    if (tid < 8) {
        float P = 0.f, N = 0.f;
        for (int cc = 0; cc < 32; cc++) { P += sp[cc * 8 + tid]; N += sn[cc * 8 + tid]; }
        float base = P + b_r[tid];
        float nl = N + b_noise[tid];
        float ns = log1pf(expf(-fabsf(nl))) + fmaxf(nl, 0.f);   // softplus
        slog[tid] = base + noise[b * 8 + tid] * ns;
    }
    __syncthreads();
    if (tid == 0) {
        float lg[8], mx = -FLT_MAX;
        #pragma unroll
        for (int i = 0; i < 8; i++) { lg[i] = slog[i]; mx = fmaxf(mx, lg[i]); }
        float es = 0.f, pw[8];
        #pragma unroll
        for (int i = 0; i < 8; i++) { pw[i] = expf(lg[i] - mx); es += pw[i]; }
        #pragma unroll
        for (int i = 0; i < 8; i++) pw[i] /= es;
        #pragma unroll
        for (int i = 0; i < 8; i++) {
            int rank = 0;
            #pragma unroll
            for (int j = 0; j < 8; j++)
                if (pw[j] > pw[i] || (pw[j] == pw[i] && j < i)) rank++;
            out[b * 8 + i] = (rank < 4) ? pw[i] : 0.f;
        }
    }
}

// ---------------- launch ----------------
extern "C" void kernel_launch(void* const* d_in, const int* in_sizes, int n_in,
                              void* d_out, int out_size) {
    const float* x       = (const float*)d_in[0];
    const float* noise   = (const float*)d_in[1];
    const float* W_r     = (const float*)d_in[2];
    const float* b_r     = (const float*)d_in[3];
    const float* W_noise = (const float*)d_in[4];
    const float* b_noise = (const float*)d_in[5];
    const float* W_trend = (const float*)d_in[6];
    const float* b_trend = (const float*)d_in[7];
    const float* W_lin   = (const float*)d_in[8];
    const float* b_lin   = (const float*)d_in[9];
    float* out = (float*)d_out;

    k_fused<<<BB * DD / 4, 256>>>(x, W_trend, b_trend, W_lin);
    k_router<<<16, 256>>>(noise, W_r, b_r, W_noise, b_noise, b_lin, out);
}

// round 12
// speedup vs baseline: 1.1879x; 1.0754x over previous
#include <cuda_runtime.h>
#include <math.h>
#include <float.h>

#define BB 16
#define TT 512
#define DD 512

typedef unsigned long long ull;
__device__ __forceinline__ ull umax64(ull a, ull b) { return a > b ? a : b; }
__device__ __forceinline__ ull umin64(ull a, ull b) { return a < b ? a : b; }
__device__ __forceinline__ float ex2f(float x) {
    float y; asm("ex2.approx.ftz.f32 %0, %1;" : "=f"(y) : "f"(x)); return y;
}

// ---------------- scratch (static __device__ — no allocations) ----------------
__device__ float g_xtr[BB * DD];                    // x_trans (before +b_lin)

// ---------------- fused: 4 series per block, 2 packed real FFTs (radix-4) ----------------
__global__ void __launch_bounds__(256, 6) k_fused(const float* __restrict__ x,
                                                  const float* __restrict__ W_trend,
                                                  const float* __restrict__ b_trend,
                                                  const float* __restrict__ W_lin) {
    __shared__ __align__(16) float2 s_pp[2][1024];  // FFT ping-pong; buf0 = spectrum, buf1 later = rem
    __shared__ float2 s_trig[512];      // {cos, sin}(2*pi*j/512)
    __shared__ __align__(16) float s_cse[4][548];   // extended cumsum: index i+16, i in [-16, 531]
    __shared__ int    s_wk[4][4];
    __shared__ float  s_wr[4][4], s_wi[4][4];
    __shared__ float  s_red[4][8];

    int tid = threadIdx.x;
    int lane = tid & 31, w = tid >> 5;
    int bidx = blockIdx.x;
    int b  = bidx >> 7;                 // 128 blocks per batch (512/4)
    int d0 = (bidx & 127) << 2;

    // issue strided global loads first (latency hidden by trig below)
    const float* xp = x + ((size_t)b * TT + tid) * DD + d0;
    float4 v0 = *(const float4*)xp;
    float4 v1 = *(const float4*)(xp + (size_t)256 * DD);

    // trig table: one sincospif; second half via cos(pi+a) = -cos(a)
    {
        float s0, c0;
        sincospif((float)tid * (1.0f / 256.0f), &s0, &c0);
        s_trig[tid]       = make_float2(c0, s0);
        s_trig[tid + 256] = make_float2(-c0, -s0);
    }

    // x values for this thread's positions (t = tid, tid+256), all 4 series -> registers
    float xv[4][2];
    xv[0][0] = v0.x; xv[1][0] = v0.y; xv[2][0] = v0.z; xv[3][0] = v0.w;
    xv[0][1] = v1.x; xv[1][1] = v1.y; xv[2][1] = v1.z; xv[3][1] = v1.w;

    // pack fft0 = x(d0) + i x(d0+1), fft1 = x(d0+2) + i x(d0+3)
    s_pp[0][tid]             = make_float2(v0.x, v0.y);
    s_pp[0][tid + 256]       = make_float2(v1.x, v1.y);
    s_pp[0][512 + tid]       = make_float2(v0.z, v0.w);
    s_pp[0][512 + tid + 256] = make_float2(v1.z, v1.w);

    // ---- 4 radix-4 Stockham stages (Ns = 1,4,16,64), 2 FFTs in parallel ----
    int cur = 0;
    #pragma unroll
    for (int st = 0; st < 4; st++) {
        int Ns = 1 << (2 * st);
        int shiftm = 7 - 2 * st;         // twiddle idx = k * (128/Ns)
        __syncthreads();
        int f = tid >> 7;                // fft id
        int j = tid & 127;
        int k = j & (Ns - 1);
        int base = f << 9;
        float2 a0 = s_pp[cur][base + j];
        float2 a1 = s_pp[cur][base + j + 128];
        float2 a2 = s_pp[cur][base + j + 256];
        float2 a3 = s_pp[cur][base + j + 384];
        int m = k << shiftm;
        float2 w1 = s_trig[m], w2 = s_trig[2 * m], w3 = s_trig[3 * m];
        // t = W*x, W = (c, -s)
        float t1r = w1.x * a1.x + w1.y * a1.y, t1i = w1.x * a1.y - w1.y * a1.x;
        float t2r = w2.x * a2.x + w2.y * a2.y, t2i = w2.x * a2.y - w2.y * a2.x;
        float t3r = w3.x * a3.x + w3.y * a3.y, t3i = w3.x * a3.y - w3.y * a3.x;
        float y0r = a0.x + t1r + t2r + t3r, y0i = a0.y + t1i + t2i + t3i;
        float y2r = a0.x - t1r + t2r - t3r, y2i = a0.y - t1i + t2i - t3i;
        float y1r = a0.x + t1i - t2r - t3i, y1i = a0.y - t1r - t2i + t3r;
        float y3r = a0.x - t1i - t2r + t3i, y3i = a0.y + t1r - t2i - t3r;
        int o = base + 4 * j - 3 * k;
        int nxt = cur ^ 1;
        s_pp[nxt][o]          = make_float2(y0r, y0i);
        s_pp[nxt][o + Ns]     = make_float2(y1r, y1i);
        s_pp[nxt][o + 2 * Ns] = make_float2(y2r, y2i);
        s_pp[nxt][o + 3 * Ns] = make_float2(y3r, y3i);
        cur = nxt;
    }
    // ---- final radix-2 stage (Ns = 256), each thread does both FFTs ----
    __syncthreads();
    {
        int k = tid;
        float2 wv = s_trig[k];
        int nxt = cur ^ 1;
        #pragma unroll
        for (int f = 0; f < 2; f++) {
            int base = f << 9;
            float2 a = s_pp[cur][base + k];
            float2 c = s_pp[cur][base + k + 256];
            float tr = wv.x * c.x + wv.y * c.y, ti = wv.x * c.y - wv.y * c.x;
            s_pp[nxt][base + k]       = make_float2(a.x + tr, a.y + ti);
            s_pp[nxt][base + k + 256] = make_float2(a.x - tr, a.y - ti);
        }
        cur = nxt;                        // final spectrum in buf 1
    }
    __syncthreads();

    // ---- unpack: spectrum of series s as float2 at s_pp[0][s*256 + k], k=1..255 ----
    if (tid >= 1) {
        int k = tid, mk = 512 - tid;
        #pragma unroll
        for (int f = 0; f < 2; f++) {
            int base = f << 9;
            float2 Z = s_pp[1][base + k];
            float2 M = s_pp[1][base + mk];
            float Xar = 0.5f * (Z.x + M.x), Xai = 0.5f * (Z.y - M.y);
            float Xbr = 0.5f * (Z.y + M.y), Xbi = 0.5f * (M.x - Z.x);
            s_pp[0][(2 * f) * 256 + k]     = make_float2(Xar, Xai);
            s_pp[0][(2 * f + 1) * 256 + k] = make_float2(Xbr, Xbi);
        }
    }
    __syncthreads();

    // ---- warp top-4 per series (warps 0..3), key = amp_bits<<32 | (511-k) ----
    if (w < 4) {
        const float2* Xs = &s_pp[0][w * 256];
        ull c0 = 0, c1 = 0, c2 = 0, c3 = 0;
        #pragma unroll
        for (int j = 0; j < 8; j++) {
            int k = lane + 32 * j;
            float2 X = Xs[k];
            float a = X.x * X.x + X.y * X.y;
            ull p = (k == 0) ? 0ull
                  : (((ull)__float_as_uint(a) << 32) | (ull)(511 - k));
            ull t;
            t = umin64(c0, p); c0 = umax64(c0, p); p = t;
            t = umin64(c1, p); c1 = umax64(c1, p); p = t;
            t = umin64(c2, p); c2 = umax64(c2, p); p = t;
            c3 = umax64(c3, p);
        }
        #pragma unroll
        for (int off = 16; off; off >>= 1) {
            ull o0 = __shfl_xor_sync(0xffffffffu, c0, off);
            ull o1 = __shfl_xor_sync(0xffffffffu, c1, off);
            ull o2 = __shfl_xor_sync(0xffffffffu, c2, off);
            ull o3 = __shfl_xor_sync(0xffffffffu, c3, off);
            bool mf = c0 > o0;
            ull u0 = mf ? c0 : o0, u1 = mf ? c1 : o1, u2 = mf ? c2 : o2, u3 = mf ? c3 : o3;
            ull v0_ = mf ? o0 : c0, v1_ = mf ? o1 : c1, v2_ = mf ? o2 : c2, v3_ = mf ? o3 : c3;
            ull A0 = umax64(u0, v3_), A1 = umax64(u1, v2_);
            ull A2 = umax64(u2, v1_), A3 = umax64(u3, v0_);
            ull B0 = umax64(A0, A2), B2 = umin64(A0, A2);
            ull B1 = umax64(A1, A3), B3 = umin64(A1, A3);
            c0 = umax64(B0, B1); c1 = umin64(B0, B1);
            c2 = umax64(B2, B3); c3 = umin64(B2, B3);
        }
        if (lane == 0) {
            int k0 = 511 - (int)(c0 & 0xffffffffull);
            int k1 = 511 - (int)(c1 & 0xffffffffull);
            int k2 = 511 - (int)(c2 & 0xffffffffull);
            int k3 = 511 - (int)(c3 & 0xffffffffull);
            float2 X0 = Xs[k0], X1 = Xs[k1], X2 = Xs[k2], X3 = Xs[k3];
            s_wk[w][0] = k0; s_wr[w][0] = X0.x; s_wi[w][0] = X0.y;
            s_wk[w][1] = k1; s_wr[w][1] = X1.x; s_wi[w][1] = X1.y;
            s_wk[w][2] = k2; s_wr[w][2] = X2.x; s_wi[w][2] = X2.y;
            s_wk[w][3] = k3; s_wr[w][3] = X3.x; s_wi[w][3] = X3.y;
        }
    }
    __syncthreads();

    // ---- season + remainder; rem kept in registers AND stored (float) into buf1 ----
    float* remall = (float*)&s_pp[1][0];
    float remv[4][2];
    #pragma unroll
    for (int s = 0; s < 4; s++) {
        int   kk0 = s_wk[s][0], kk1 = s_wk[s][1], kk2 = s_wk[s][2], kk3 = s_wk[s][3];
        float r0 = s_wr[s][0], r1 = s_wr[s][1], r2 = s_wr[s][2], r3 = s_wr[s][3];
        float i0 = s_wi[s][0], i1 = s_wi[s][1], i2 = s_wi[s][2], i3 = s_wi[s][3];
        float* remp = remall + s * 512;
        #pragma unroll
        for (int tt = 0; tt < 2; tt++) {
            int t = tid + tt * 256;
            float2 T0 = s_trig[(kk0 * t) & 511];
            float2 T1 = s_trig[(kk1 * t) & 511];
            float2 T2 = s_trig[(kk2 * t) & 511];
            float2 T3 = s_trig[(kk3 * t) & 511];
            float se = r0 * T0.x - i0 * T0.y
                     + r1 * T1.x - i1 * T1.y
                     + r2 * T2.x - i2 * T2.y
                     + r3 * T3.x - i3 * T3.y;
            float rv = xv[s][tt] - se * (2.0f / 512.0f);
            remv[s][tt] = rv;
            remp[t] = rv;
        }
    }
    __syncthreads();

    // ---- 4 parallel cumsums, float4 pass-based scan (4 passes of 128) ----
    // cs_ext[i] (i in [-16,531]) at s_cse[s][16+i]:
    //   i<0: i*rem0 ; 0..512: exclusive cumsum ; >512: total + (i-512)*remL
    if (w < 4) {
        const float4* rm4 = (const float4*)(remall + w * 512);
        float* cse = s_cse[w];
        float offset = 0.f;
        #pragma unroll
        for (int i = 0; i < 4; i++) {
            float4 v = rm4[i * 32 + lane];
            float sv = v.x + v.y + v.z + v.w;
            float inc = sv;
            #pragma unroll
            for (int sft = 1; sft < 32; sft <<= 1) {
                float u = __shfl_up_sync(0xffffffffu, inc, sft);
                if (lane >= sft) inc += u;
            }
            float excl = offset + (inc - sv);
            float4 o4;
            o4.x = excl;
            o4.y = excl + v.x;
            o4.z = o4.y + v.y;
            o4.w = o4.z + v.z;
            ((float4*)(cse + 16))[i * 32 + lane] = o4;
            offset += __shfl_sync(0xffffffffu, inc, 31);
        }
        if (lane == 31) cse[16 + 512] = offset;             // total
        if (lane < 16) {
            float rem0 = remall[w * 512], remL = remall[w * 512 + 511];
            cse[lane] = (float)(lane - 16) * rem0;                      // i = lane-16
            cse[16 + 513 + lane] = offset + (float)(lane + 1) * remL;   // i = 513+lane
        }
    }
    __syncthreads();

    // ---- trend + W_lin reduce, 4 series (rem & x from registers) ----
    const float LOG2E = 1.44269504f;
    float Wt2[6], bt2[6];
    #pragma unroll
    for (int j = 0; j < 6; j++) { Wt2[j] = W_trend[j] * LOG2E; bt2[j] = b_trend[j] * LOG2E; }
    const int   koff[6] = {2, 4, 6, 8, 12, 16};        // k/2
    const float inv[6] = {0.25f, 0.125f, 1.f / 12.f, 0.0625f, 1.f / 24.f, 0.03125f};
    float wl0 = W_lin[tid], wl1 = W_lin[tid + 256];

    float accv[4];
    #pragma unroll
    for (int s = 0; s < 4; s++) {
        const float* cse = s_cse[s] + 16;
        float acc = 0.f;
        #pragma unroll
        for (int tt = 0; tt < 2; tt++) {
            int t = tid + tt * 256;
            float rem = remv[s][tt];
            const float* cp = cse + t;
            float es = 0.f, ws = 0.f;
            #pragma unroll
            for (int j = 0; j < 6; j++) {
                float ssum = cp[koff[j]] - cp[-koff[j]];
                float e = ex2f(fmaf(rem, Wt2[j], bt2[j]));
                es += e;
                ws = fmaf(e, ssum * inv[j], ws);
            }
            float trend = __fdividef(ws, es);
            float xsum = 2.0f * xv[s][tt] - rem + trend;
            acc = fmaf(xsum, (tt ? wl1 : wl0), acc);
        }
        accv[s] = acc;
    }

    #pragma unroll
    for (int o = 16; o > 0; o >>= 1) {
        accv[0] += __shfl_down_sync(0xffffffffu, accv[0], o);
        accv[1] += __shfl_down_sync(0xffffffffu, accv[1], o);
        accv[2] += __shfl_down_sync(0xffffffffu, accv[2], o);
        accv[3] += __shfl_down_sync(0xffffffffu, accv[3], o);
    }
    if (lane == 0) {
        s_red[0][w] = accv[0]; s_red[1][w] = accv[1];
        s_red[2][w] = accv[2]; s_red[3][w] = accv[3];
    }
    __syncthreads();
    if (tid < 4) {
        float s = 0.f;
        #pragma unroll
        for (int ww = 0; ww < 8; ww++) s += s_red[tid][ww];
        g_xtr[blockIdx.x * 4 + tid] = s;
    }
}

// ---------------- final routing: (B,D)->(B,8), softplus noise, softmax, top-4 ----------------
__global__ void k_router(const float* __restrict__ noise, const float* __restrict__ W_r,
                         const float* __restrict__ b_r, const float* __restrict__ W_noise,
                         const float* __restrict__ b_noise, const float* __restrict__ b_lin,
                         float* __restrict__ out) {
    int b = blockIdx.x;
    int tid = threadIdx.x;
    int m = tid & 7, c = tid >> 3;
    __shared__ float sp[256], sn[256];
    __shared__ float slog[8];
    const float* xt = g_xtr + b * DD;
    float blin = b_lin[0];
    float p = 0.f, pn = 0.f;
    #pragma unroll
    for (int i = 0; i < 16; i++) {
        int d = c * 16 + i;
        float v = xt[d] + blin;
        p  = fmaf(v, W_r[d * 8 + m], p);
        pn = fmaf(v, W_noise[d * 8 + m], pn);
    }
    sp[tid] = p; sn[tid] = pn;
    __syncthreads();
    if (tid < 8) {
        float P = 0.f, N = 0.f;
        for (int cc = 0; cc < 32; cc++) { P += sp[cc * 8 + tid]; N += sn[cc * 8 + tid]; }
        float base = P + b_r[tid];
        float nl = N + b_noise[tid];
        float ns = log1pf(expf(-fabsf(nl))) + fmaxf(nl, 0.f);   // softplus
        slog[tid] = base + noise[b * 8 + tid] * ns;
    }
    __syncthreads();
    if (tid == 0) {
        float lg[8], mx = -FLT_MAX;
        #pragma unroll
        for (int i = 0; i < 8; i++) { lg[i] = slog[i]; mx = fmaxf(mx, lg[i]); }
        float es = 0.f, pw[8];
        #pragma unroll
        for (int i = 0; i < 8; i++) { pw[i] = expf(lg[i] - mx); es += pw[i]; }
        #pragma unroll
        for (int i = 0; i < 8; i++) pw[i] /= es;
        #pragma unroll
        for (int i = 0; i < 8; i++) {
            int rank = 0;
            #pragma unroll
            for (int j = 0; j < 8; j++)
                if (pw[j] > pw[i] || (pw[j] == pw[i] && j < i)) rank++;
            out[b * 8 + i] = (rank < 4) ? pw[i] : 0.f;
        }
    }
}

// ---------------- launch ----------------
extern "C" void kernel_launch(void* const* d_in, const int* in_sizes, int n_in,
                              void* d_out, int out_size) {
    const float* x       = (const float*)d_in[0];
    const float* noise   = (const float*)d_in[1];
    const float* W_r     = (const float*)d_in[2];
    const float* b_r     = (const float*)d_in[3];
    const float* W_noise = (const float*)d_in[4];
    const float* b_noise = (const float*)d_in[5];
    const float* W_trend = (const float*)d_in[6];
    const float* b_trend = (const float*)d_in[7];
    const float* W_lin   = (const float*)d_in[8];
    const float* b_lin   = (const float*)d_in[9];
    float* out = (float*)d_out;

    k_fused<<<BB * DD / 4, 256>>>(x, W_trend, b_trend, W_lin);
    k_router<<<16, 256>>>(noise, W_r, b_r, W_noise, b_noise, b_lin, out);
}

// round 14
// speedup vs baseline: 1.2915x; 1.0872x over previous
#include <cuda_runtime.h>
#include <math.h>
#include <float.h>

#define BB 16
#define TT 512
#define DD 512

typedef unsigned long long ull;
__device__ __forceinline__ ull umax64(ull a, ull b) { return a > b ? a : b; }
__device__ __forceinline__ ull umin64(ull a, ull b) { return a < b ? a : b; }
__device__ __forceinline__ float ex2f(float x) {
    float y; asm("ex2.approx.ftz.f32 %0, %1;" : "=f"(y) : "f"(x)); return y;
}

// ---------------- scratch (static __device__ — no allocations) ----------------
__device__ float g_xtr[BB * DD];                    // x_trans (before +b_lin)

// ---------------- fused: 4 series per block, 2 packed real FFTs (radix-4) ----------------
__global__ void __launch_bounds__(256, 6) k_fused(const float* __restrict__ x,
                                                  const float* __restrict__ W_trend,
                                                  const float* __restrict__ b_trend,
                                                  const float* __restrict__ W_lin) {
    __shared__ __align__(16) float2 s_pp[2][1024];  // FFT ping-pong; buf0 = spectrum, buf1 later = rem
    __shared__ float2 s_trig[512];      // {cos, sin}(2*pi*j/512)
    __shared__ __align__(16) float s_cse[4][548];   // extended cumsum: index i+16, i in [-16, 531]
    __shared__ int    s_wk[4][4];
    __shared__ float  s_wr[4][4], s_wi[4][4];
    __shared__ float  s_red[4][8];

    int tid = threadIdx.x;
    int lane = tid & 31, w = tid >> 5;
    int bidx = blockIdx.x;
    int b  = bidx >> 7;                 // 128 blocks per batch (512/4)
    int d0 = (bidx & 127) << 2;

    // issue strided global loads first (latency hidden by trig below)
    const float* xp = x + ((size_t)b * TT + tid) * DD + d0;
    float4 v0 = *(const float4*)xp;
    float4 v1 = *(const float4*)(xp + (size_t)256 * DD);

    // trig table: one sincospif; second half via cos(pi+a) = -cos(a)
    {
        float s0, c0;
        sincospif((float)tid * (1.0f / 256.0f), &s0, &c0);
        s_trig[tid]       = make_float2(c0, s0);
        s_trig[tid + 256] = make_float2(-c0, -s0);
    }

    // x values for this thread's positions (t = tid, tid+256), all 4 series -> registers
    float xv[4][2];
    xv[0][0] = v0.x; xv[1][0] = v0.y; xv[2][0] = v0.z; xv[3][0] = v0.w;
    xv[0][1] = v1.x; xv[1][1] = v1.y; xv[2][1] = v1.z; xv[3][1] = v1.w;

    // pack fft0 = x(d0) + i x(d0+1), fft1 = x(d0+2) + i x(d0+3)
    s_pp[0][tid]             = make_float2(v0.x, v0.y);
    s_pp[0][tid + 256]       = make_float2(v1.x, v1.y);
    s_pp[0][512 + tid]       = make_float2(v0.z, v0.w);
    s_pp[0][512 + tid + 256] = make_float2(v1.z, v1.w);

    __syncthreads();
    // ---- radix-4 stage 0 (Ns = 1): all twiddles are (1,0) -> pure adds ----
    {
        int f = tid >> 7;
        int j = tid & 127;
        int base = f << 9;
        float2 a0 = s_pp[0][base + j];
        float2 a1 = s_pp[0][base + j + 128];
        float2 a2 = s_pp[0][base + j + 256];
        float2 a3 = s_pp[0][base + j + 384];
        float y0r = a0.x + a1.x + a2.x + a3.x, y0i = a0.y + a1.y + a2.y + a3.y;
        float y2r = a0.x - a1.x + a2.x - a3.x, y2i = a0.y - a1.y + a2.y - a3.y;
        float y1r = a0.x + a1.y - a2.x - a3.y, y1i = a0.y - a1.x - a2.y + a3.x;
        float y3r = a0.x - a1.y - a2.x + a3.y, y3i = a0.y + a1.x - a2.y - a3.x;
        int o = base + 4 * j;
        s_pp[1][o]     = make_float2(y0r, y0i);
        s_pp[1][o + 1] = make_float2(y1r, y1i);
        s_pp[1][o + 2] = make_float2(y2r, y2i);
        s_pp[1][o + 3] = make_float2(y3r, y3i);
    }
    int cur = 1;
    // ---- radix-4 stages 1..3 (Ns = 4,16,64) ----
    #pragma unroll
    for (int st = 1; st < 4; st++) {
        int Ns = 1 << (2 * st);
        int shiftm = 7 - 2 * st;         // twiddle idx = k * (128/Ns)
        __syncthreads();
        int f = tid >> 7;                // fft id
        int j = tid & 127;
        int k = j & (Ns - 1);
        int base = f << 9;
        float2 a0 = s_pp[cur][base + j];
        float2 a1 = s_pp[cur][base + j + 128];
        float2 a2 = s_pp[cur][base + j + 256];
        float2 a3 = s_pp[cur][base + j + 384];
        int m = k << shiftm;
        float2 w1 = s_trig[m], w2 = s_trig[2 * m], w3 = s_trig[3 * m];
        // t = W*x, W = (c, -s)
        float t1r = w1.x * a1.x + w1.y * a1.y, t1i = w1.x * a1.y - w1.y * a1.x;
        float t2r = w2.x * a2.x + w2.y * a2.y, t2i = w2.x * a2.y - w2.y * a2.x;
        float t3r = w3.x * a3.x + w3.y * a3.y, t3i = w3.x * a3.y - w3.y * a3.x;
        float y0r = a0.x + t1r + t2r + t3r, y0i = a0.y + t1i + t2i + t3i;
        float y2r = a0.x - t1r + t2r - t3r, y2i = a0.y - t1i + t2i - t3i;
        float y1r = a0.x + t1i - t2r - t3i, y1i = a0.y - t1r - t2i + t3r;
        float y3r = a0.x - t1i - t2r + t3i, y3i = a0.y + t1r - t2i - t3r;
        int o = base + 4 * j - 3 * k;
        int nxt = cur ^ 1;
        s_pp[nxt][o]          = make_float2(y0r, y0i);
        s_pp[nxt][o + Ns]     = make_float2(y1r, y1i);
        s_pp[nxt][o + 2 * Ns] = make_float2(y2r, y2i);
        s_pp[nxt][o + 3 * Ns] = make_float2(y3r, y3i);
        cur = nxt;
    }
    // ---- final radix-2 stage (Ns = 256), each thread does both FFTs ----
    __syncthreads();
    {
        int k = tid;
        float2 wv = s_trig[k];
        int nxt = cur ^ 1;
        #pragma unroll
        for (int f = 0; f < 2; f++) {
            int base = f << 9;
            float2 a = s_pp[cur][base + k];
            float2 c = s_pp[cur][base + k + 256];
            float tr = wv.x * c.x + wv.y * c.y, ti = wv.x * c.y - wv.y * c.x;
            s_pp[nxt][base + k]       = make_float2(a.x + tr, a.y + ti);
            s_pp[nxt][base + k + 256] = make_float2(a.x - tr, a.y - ti);
        }
        cur = nxt;                        // final spectrum in buf 1
    }
    __syncthreads();

    // ---- unpack: spectrum of series s as float2 at s_pp[0][s*256 + k], k=1..255 ----
    if (tid >= 1) {
        int k = tid, mk = 512 - tid;
        #pragma unroll
        for (int f = 0; f < 2; f++) {
            int base = f << 9;
            float2 Z = s_pp[1][base + k];
            float2 M = s_pp[1][base + mk];
            float Xar = 0.5f * (Z.x + M.x), Xai = 0.5f * (Z.y - M.y);
            float Xbr = 0.5f * (Z.y + M.y), Xbi = 0.5f * (M.x - Z.x);
            s_pp[0][(2 * f) * 256 + k]     = make_float2(Xar, Xai);
            s_pp[0][(2 * f + 1) * 256 + k] = make_float2(Xbr, Xbi);
        }
    }
    __syncthreads();

    // ---- warp top-4 per series (warps 0..3), key = amp_bits<<32 | (511-k) ----
    if (w < 4) {
        const float2* Xs = &s_pp[0][w * 256];
        ull c0 = 0, c1 = 0, c2 = 0, c3 = 0;
        #pragma unroll
        for (int j = 0; j < 8; j++) {
            int k = lane + 32 * j;
            float2 X = Xs[k];
            float a = X.x * X.x + X.y * X.y;
            ull p = (k == 0) ? 0ull
                  : (((ull)__float_as_uint(a) << 32) | (ull)(511 - k));
            ull t;
            t = umin64(c0, p); c0 = umax64(c0, p); p = t;
            t = umin64(c1, p); c1 = umax64(c1, p); p = t;
            t = umin64(c2, p); c2 = umax64(c2, p); p = t;
            c3 = umax64(c3, p);
        }
        #pragma unroll
        for (int off = 16; off; off >>= 1) {
            ull o0 = __shfl_xor_sync(0xffffffffu, c0, off);
            ull o1 = __shfl_xor_sync(0xffffffffu, c1, off);
            ull o2 = __shfl_xor_sync(0xffffffffu, c2, off);
            ull o3 = __shfl_xor_sync(0xffffffffu, c3, off);
            bool mf = c0 > o0;
            ull u0 = mf ? c0 : o0, u1 = mf ? c1 : o1, u2 = mf ? c2 : o2, u3 = mf ? c3 : o3;
            ull v0_ = mf ? o0 : c0, v1_ = mf ? o1 : c1, v2_ = mf ? o2 : c2, v3_ = mf ? o3 : c3;
            ull A0 = umax64(u0, v3_), A1 = umax64(u1, v2_);
            ull A2 = umax64(u2, v1_), A3 = umax64(u3, v0_);
            ull B0 = umax64(A0, A2), B2 = umin64(A0, A2);
            ull B1 = umax64(A1, A3), B3 = umin64(A1, A3);
            c0 = umax64(B0, B1); c1 = umin64(B0, B1);
            c2 = umax64(B2, B3); c3 = umin64(B2, B3);
        }
        if (lane == 0) {
            int k0 = 511 - (int)(c0 & 0xffffffffull);
            int k1 = 511 - (int)(c1 & 0xffffffffull);
            int k2 = 511 - (int)(c2 & 0xffffffffull);
            int k3 = 511 - (int)(c3 & 0xffffffffull);
            float2 X0 = Xs[k0], X1 = Xs[k1], X2 = Xs[k2], X3 = Xs[k3];
            s_wk[w][0] = k0; s_wr[w][0] = X0.x; s_wi[w][0] = X0.y;
            s_wk[w][1] = k1; s_wr[w][1] = X1.x; s_wi[w][1] = X1.y;
            s_wk[w][2] = k2; s_wr[w][2] = X2.x; s_wi[w][2] = X2.y;
            s_wk[w][3] = k3; s_wr[w][3] = X3.x; s_wi[w][3] = X3.y;
        }
    }
    __syncthreads();

    // ---- season + remainder with parity trick: term(t+256) = ±term(t) by kk parity ----
    float* remall = (float*)&s_pp[1][0];
    float remv[4][2];
    #pragma unroll
    for (int s = 0; s < 4; s++) {
        float se0 = 0.f, se1 = 0.f;
        #pragma unroll
        for (int j = 0; j < 4; j++) {
            int   kk = s_wk[s][j];
            float rr = s_wr[s][j], ii = s_wi[s][j];
            float2 T = s_trig[(kk * tid) & 511];
            float term = rr * T.x - ii * T.y;
            se0 += term;
            se1 += (kk & 1) ? -term : term;
        }
        float rv0 = xv[s][0] - se0 * (2.0f / 512.0f);
        float rv1 = xv[s][1] - se1 * (2.0f / 512.0f);
        remv[s][0] = rv0; remv[s][1] = rv1;
        float* remp = remall + s * 512;
        remp[tid] = rv0;
        remp[tid + 256] = rv1;
    }
    __syncthreads();

    // ---- 4 parallel cumsums, float4 pass-based scan (4 passes of 128) ----
    // cs_ext[i] (i in [-16,531]) at s_cse[s][16+i]:
    //   i<0: i*rem0 ; 0..512: exclusive cumsum ; >512: total + (i-512)*remL
    if (w < 4) {
        const float4* rm4 = (const float4*)(remall + w * 512);
        float* cse = s_cse[w];
        float offset = 0.f;
        #pragma unroll
        for (int i = 0; i < 4; i++) {
            float4 v = rm4[i * 32 + lane];
            float sv = v.x + v.y + v.z + v.w;
            float inc = sv;
            #pragma unroll
            for (int sft = 1; sft < 32; sft <<= 1) {
                float u = __shfl_up_sync(0xffffffffu, inc, sft);
                if (lane >= sft) inc += u;
            }
            float excl = offset + (inc - sv);
            float4 o4;
            o4.x = excl;
            o4.y = excl + v.x;
            o4.z = o4.y + v.y;
            o4.w = o4.z + v.z;
            ((float4*)(cse + 16))[i * 32 + lane] = o4;
            offset += __shfl_sync(0xffffffffu, inc, 31);
        }
        if (lane == 31) cse[16 + 512] = offset;             // total
        if (lane < 16) {
            float rem0 = remall[w * 512], remL = remall[w * 512 + 511];
            cse[lane] = (float)(lane - 16) * rem0;                      // i = lane-16
            cse[16 + 513 + lane] = offset + (float)(lane + 1) * remL;   // i = 513+lane
        }
    }
    __syncthreads();

    // ---- trend + W_lin reduce, 4 series (rem & x from registers) ----
    const float LOG2E = 1.44269504f;
    float Wt2[6], bt2[6];
    #pragma unroll
    for (int j = 0; j < 6; j++) { Wt2[j] = W_trend[j] * LOG2E; bt2[j] = b_trend[j] * LOG2E; }
    const int   koff[6] = {2, 4, 6, 8, 12, 16};        // k/2
    const float inv[6] = {0.25f, 0.125f, 1.f / 12.f, 0.0625f, 1.f / 24.f, 0.03125f};
    float wl0 = W_lin[tid], wl1 = W_lin[tid + 256];

    float accv[4];
    #pragma unroll
    for (int s = 0; s < 4; s++) {
        const float* cse = s_cse[s] + 16;
        float acc = 0.f;
        #pragma unroll
        for (int tt = 0; tt < 2; tt++) {
            int t = tid + tt * 256;
            float rem = remv[s][tt];
            const float* cp = cse + t;
            float es = 0.f, ws = 0.f;
            #pragma unroll
            for (int j = 0; j < 6; j++) {
                float ssum = cp[koff[j]] - cp[-koff[j]];
                float e = ex2f(fmaf(rem, Wt2[j], bt2[j]));
                es += e;
                ws = fmaf(e, ssum * inv[j], ws);
            }
            float trend = __fdividef(ws, es);
            float xsum = 2.0f * xv[s][tt] - rem + trend;
            acc = fmaf(xsum, (tt ? wl1 : wl0), acc);
        }
        accv[s] = acc;
    }

    #pragma unroll
    for (int o = 16; o > 0; o >>= 1) {
        accv[0] += __shfl_down_sync(0xffffffffu, accv[0], o);
        accv[1] += __shfl_down_sync(0xffffffffu, accv[1], o);
        accv[2] += __shfl_down_sync(0xffffffffu, accv[2], o);
        accv[3] += __shfl_down_sync(0xffffffffu, accv[3], o);
    }
    if (lane == 0) {
        s_red[0][w] = accv[0]; s_red[1][w] = accv[1];
        s_red[2][w] = accv[2]; s_red[3][w] = accv[3];
    }
    __syncthreads();
    if (tid < 4) {
        float s = 0.f;
        #pragma unroll
        for (int ww = 0; ww < 8; ww++) s += s_red[tid][ww];
        g_xtr[blockIdx.x * 4 + tid] = s;
    }
}

// ---------------- final routing: warp-per-expert GEMV + parallel softmax/top-4 ----------------
__global__ void k_router(const float* __restrict__ noise, const float* __restrict__ W_r,
                         const float* __restrict__ b_r, const float* __restrict__ W_noise,
                         const float* __restrict__ b_noise, const float* __restrict__ b_lin,
                         float* __restrict__ out) {
    int b = blockIdx.x;
    int tid = threadIdx.x;
    int lane = tid & 31, m = tid >> 5;   // warp m owns expert m
    __shared__ float slog[8];
    const float* xt = g_xtr + b * DD;
    float blin = b_lin[0];
    float p = 0.f, pn = 0.f;
    #pragma unroll
    for (int i = 0; i < 16; i++) {
        int d = lane + 32 * i;
        float v = xt[d] + blin;
        p  = fmaf(v, W_r[d * 8 + m], p);
        pn = fmaf(v, W_noise[d * 8 + m], pn);
    }
    #pragma unroll
    for (int o = 16; o > 0; o >>= 1) {
        p  += __shfl_down_sync(0xffffffffu, p, o);
        pn += __shfl_down_sync(0xffffffffu, pn, o);
    }
    if (lane == 0) {
        float base = p + b_r[m];
        float nl = pn + b_noise[m];
        float ns = log1pf(expf(-fabsf(nl))) + fmaxf(nl, 0.f);   // softplus
        slog[m] = base + noise[b * 8 + m] * ns;
    }
    __syncthreads();
    if (tid < 8) {
        float lg[8], mx = -FLT_MAX;
        #pragma unroll
        for (int i = 0; i < 8; i++) { lg[i] = slog[i]; mx = fmaxf(mx, lg[i]); }
        float es = 0.f;
        #pragma unroll
        for (int i = 0; i < 8; i++) es += expf(lg[i] - mx);
        float pwi = expf(lg[tid] - mx) / es;
        // rank on logits (softmax monotonic; tie semantics identical)
        int rank = 0;
        #pragma unroll
        for (int j = 0; j < 8; j++)
            if (lg[j] > lg[tid] || (lg[j] == lg[tid] && j < tid)) rank++;
        out[b * 8 + tid] = (rank < 4) ? pwi : 0.f;
    }
}

// ---------------- launch ----------------
extern "C" void kernel_launch(void* const* d_in, const int* in_sizes, int n_in,
                              void* d_out, int out_size) {
    const float* x       = (const float*)d_in[0];
    const float* noise   = (const float*)d_in[1];
    const float* W_r     = (const float*)d_in[2];
    const float* b_r     = (const float*)d_in[3];
    const float* W_noise = (const float*)d_in[4];
    const float* b_noise = (const float*)d_in[5];
    const float* W_trend = (const float*)d_in[6];
    const float* b_trend = (const float*)d_in[7];
    const float* W_lin   = (const float*)d_in[8];
    const float* b_lin   = (const float*)d_in[9];
    float* out = (float*)d_out;

    k_fused<<<BB * DD / 4, 256>>>(x, W_trend, b_trend, W_lin);
    k_router<<<16, 256>>>(noise, W_r, b_r, W_noise, b_noise, b_lin, out);
}